// round 2
// baseline (speedup 1.0000x reference)
#include <cuda_runtime.h>
#include <cstdint>

#define B_      128
#define G_      10000
#define KW_     20
#define GC_     30000
#define LAT_    2000
#define INLEN_  200000

#define BM 128
#define BN 128
#define BK 16
#define PAD 4
#define KSPLIT 15
#define KCHUNK 2000
#define ZLD 2048

// ----- scratch (static device globals; allocation-free rule) -----
__device__ float g_h[B_ * GC_];                 // encoder conv out
__device__ float g_zpart[KSPLIT * BM * ZLD];    // GEMM1 split-K partials
__device__ float g_z[B_ * LAT_];                // latent
__device__ float g_d[B_ * GC_];                 // decoder FC out

__device__ __forceinline__ float lrelu(float v) { return v >= 0.0f ? v : 0.1f * v; }

// ---------------------------------------------------------------------------
// K1: encoder grouped conv. h[b,g,c] = lrelu(sum_k x[b,g*20+k]*ew[g,c,k]+eb[g,c])
// grid (157, 128), block 192: 64 groups per block, 3 channels per group.
// ---------------------------------------------------------------------------
__global__ void __launch_bounds__(192)
enc_conv_kernel(const float* __restrict__ x, const float* __restrict__ ew,
                const float* __restrict__ eb) {
    __shared__ float sx[64 * KW_];
    const int b  = blockIdx.y;
    const int g0 = blockIdx.x * 64;
    const int ng = (G_ - g0 < 64) ? (G_ - g0) : 64;
    const int nval = ng * KW_;
    for (int i = threadIdx.x; i < nval; i += 192)
        sx[i] = x[(size_t)b * INLEN_ + (size_t)g0 * KW_ + i];
    __syncthreads();
    const int j  = threadIdx.x;
    const int gl = j / 3;
    const int c  = j - gl * 3;
    const int g  = g0 + gl;
    if (gl < ng) {
        const float* w  = ew + (size_t)g * 60 + c * 20;
        const float* xv = sx + gl * KW_;
        float acc = eb[g * 3 + c];
#pragma unroll
        for (int k = 0; k < KW_; k++) acc = fmaf(xv[k], w[k], acc);
        g_h[(size_t)b * GC_ + g * 3 + c] = lrelu(acc);
    }
}

// ---------------------------------------------------------------------------
// FFMA GEMM: C[m,n] (+)= sum_k A[m,k] * W[n,k]   (A:[128,K], W:[N,K] row-major)
// mode 0: A=g_h,  C=g_zpart + blockIdx.y*BM*ZLD (raw partial, split-K chunk)
// mode 1: A=g_z,  C=g_d, epilogue lrelu(acc + bias[n])
// block 256 threads, tile 128x128x16, thread micro-tile 8x8, double-buffered.
// ---------------------------------------------------------------------------
__global__ void __launch_bounds__(256, 2)
gemm_ffma(const float* __restrict__ Wg, const float* __restrict__ bias,
          int lda, int ldw, int ldc, int Ntot, int kchunk, int mode)
{
    __shared__ float As[2][BK][BM + PAD];
    __shared__ float Ws[2][BK][BN + PAD];

    const float* A = (mode == 0) ? g_h : g_z;
    float* C = (mode == 0) ? (g_zpart + (size_t)blockIdx.y * (BM * (size_t)ZLD))
                           : g_d;

    const int tid = threadIdx.x;
    const int n0  = blockIdx.x * BN;
    const int k0  = blockIdx.y * kchunk;
    const int T   = kchunk / BK;
    const int tx  = tid & 15;
    const int ty  = tid >> 4;

    float4 ra[2], rw[2];
    const float4 z4 = make_float4(0.f, 0.f, 0.f, 0.f);

    // ---- load tile t of A/W into prefetch regs ----
    auto ldA = [&](int t) {
#pragma unroll
        for (int u = 0; u < 2; u++) {
            int f = tid + u * 256;
            int row = f >> 2, kq = f & 3;
            ra[u] = *(const float4*)(A + (size_t)row * lda + k0 + t * BK + kq * 4);
        }
    };
    auto ldW = [&](int t) {
#pragma unroll
        for (int u = 0; u < 2; u++) {
            int f = tid + u * 256;
            int row = f >> 2, kq = f & 3;
            int n = n0 + row;
            rw[u] = (n < Ntot)
                ? *(const float4*)(Wg + (size_t)n * ldw + k0 + t * BK + kq * 4)
                : z4;
        }
    };
    auto stS = [&](int buf) {
#pragma unroll
        for (int u = 0; u < 2; u++) {
            int f = tid + u * 256;
            int row = f >> 2, kq = f & 3;
            As[buf][kq * 4 + 0][row] = ra[u].x;
            As[buf][kq * 4 + 1][row] = ra[u].y;
            As[buf][kq * 4 + 2][row] = ra[u].z;
            As[buf][kq * 4 + 3][row] = ra[u].w;
            Ws[buf][kq * 4 + 0][row] = rw[u].x;
            Ws[buf][kq * 4 + 1][row] = rw[u].y;
            Ws[buf][kq * 4 + 2][row] = rw[u].z;
            Ws[buf][kq * 4 + 3][row] = rw[u].w;
        }
    };

    float acc[8][8];
#pragma unroll
    for (int i = 0; i < 8; i++)
#pragma unroll
        for (int j = 0; j < 8; j++) acc[i][j] = 0.0f;

    ldA(0); ldW(0);
    stS(0);
    __syncthreads();

    for (int t = 0; t < T; t++) {
        const int cur = t & 1;
        if (t + 1 < T) { ldA(t + 1); ldW(t + 1); }
#pragma unroll
        for (int kk = 0; kk < BK; kk++) {
            float a_f[8], w_f[8];
            *(float4*)&a_f[0] = *(const float4*)&As[cur][kk][ty * 8];
            *(float4*)&a_f[4] = *(const float4*)&As[cur][kk][ty * 8 + 4];
            *(float4*)&w_f[0] = *(const float4*)&Ws[cur][kk][tx * 8];
            *(float4*)&w_f[4] = *(const float4*)&Ws[cur][kk][tx * 8 + 4];
#pragma unroll
            for (int i = 0; i < 8; i++)
#pragma unroll
                for (int j = 0; j < 8; j++)
                    acc[i][j] = fmaf(a_f[i], w_f[j], acc[i][j]);
        }
        if (t + 1 < T) {
            stS(cur ^ 1);
            __syncthreads();
        }
    }

    if (mode == 0) {
#pragma unroll
        for (int i = 0; i < 8; i++) {
            int m = ty * 8 + i;
            float* Crow = C + (size_t)m * ZLD + n0 + tx * 8;
            *(float4*)&Crow[0] = *(float4*)&acc[i][0];
            *(float4*)&Crow[4] = *(float4*)&acc[i][4];
        }
    } else {
#pragma unroll
        for (int i = 0; i < 8; i++) {
            int m = ty * 8 + i;
#pragma unroll
            for (int j = 0; j < 8; j++) {
                int n = n0 + tx * 8 + j;
                if (n < Ntot)
                    C[(size_t)m * ldc + n] = lrelu(acc[i][j] + bias[n]);
            }
        }
    }
}

// ---------------------------------------------------------------------------
// K3: split-K reduce + bias + leaky -> g_z
// ---------------------------------------------------------------------------
__global__ void __launch_bounds__(256)
reduce_z(const float* __restrict__ bias) {
    int idx = blockIdx.x * 256 + threadIdx.x;
    if (idx >= B_ * LAT_) return;
    int b = idx / LAT_;
    int n = idx - b * LAT_;
    float s = bias[n];
#pragma unroll
    for (int sp = 0; sp < KSPLIT; sp++)
        s += g_zpart[(size_t)sp * BM * ZLD + (size_t)b * ZLD + n];
    g_z[idx] = lrelu(s);
}

// ---------------------------------------------------------------------------
// K5: decoder grouped conv-transpose + sigmoid
// out[b, g*20+k] = sigmoid(db[g] + sum_c d[b,3g+c] * dw[g,c,k])
// ---------------------------------------------------------------------------
__global__ void __launch_bounds__(256)
dec_kernel(const float* __restrict__ dw, const float* __restrict__ db,
           float* __restrict__ out) {
    int idx = blockIdx.x * 256 + threadIdx.x;
    if (idx >= B_ * INLEN_) return;
    int b = idx / INLEN_;
    int pos = idx - b * INLEN_;
    int g = pos / KW_;
    int k = pos - g * KW_;
    const float* dd = g_d + (size_t)b * GC_ + g * 3;
    const float* w  = dw + (size_t)g * 60 + k;
    float acc = db[g];
    acc = fmaf(dd[0], w[0],  acc);
    acc = fmaf(dd[1], w[20], acc);
    acc = fmaf(dd[2], w[40], acc);
    out[idx] = 1.0f / (1.0f + __expf(-acc));
}

// ---------------------------------------------------------------------------
extern "C" void kernel_launch(void* const* d_in, const int* in_sizes, int n_in,
                              void* d_out, int out_size) {
    const float* x        = (const float*)d_in[0];
    const float* enc_w    = (const float*)d_in[1];
    const float* enc_b    = (const float*)d_in[2];
    const float* enc_fc_w = (const float*)d_in[3];
    const float* enc_fc_b = (const float*)d_in[4];
    const float* dec_fc_w = (const float*)d_in[5];
    const float* dec_fc_b = (const float*)d_in[6];
    const float* dec_w    = (const float*)d_in[7];
    const float* dec_b    = (const float*)d_in[8];
    float* out = (float*)d_out;

    // 1) encoder grouped conv -> g_h [128, 30000]
    enc_conv_kernel<<<dim3(157, 128), 192>>>(x, enc_w, enc_b);

    // 2) enc FC, split-K=15 -> g_zpart  (A=g_h [128,30000], W=[2000,30000])
    gemm_ffma<<<dim3(16, KSPLIT), 256>>>(enc_fc_w, nullptr,
                                         GC_, GC_, 0, LAT_, KCHUNK, 0);

    // 3) reduce + bias + leaky -> g_z [128, 2000]
    reduce_z<<<(B_ * LAT_ + 255) / 256, 256>>>(enc_fc_b);

    // 4) dec FC fused epilogue -> g_d [128, 30000]  (W=[30000,2000])
    gemm_ffma<<<dim3(235, 1), 256>>>(dec_fc_w, dec_fc_b,
                                     LAT_, LAT_, GC_, GC_, LAT_, 1);

    // 5) decoder conv-transpose + sigmoid -> out [128, 200000]
    dec_kernel<<<(B_ * INLEN_ + 255) / 256, 256>>>(dec_w, dec_b, out);
}

// round 8
// speedup vs baseline: 2.3206x; 2.3206x over previous
#include <cuda_runtime.h>
#include <cstdint>

#define B_      128
#define G_      10000
#define KW_     20
#define GC_     30000
#define LAT_    2000
#define INLEN_  200000

#define KSPLIT  15
#define KCHUNK  2016          // 15*2016 >= 30000
#define ZLD     2048

#define BK      32
#define SAK     36            // padded row stride (floats) -> conflict-free frags
#define TILE_F  (128 * SAK)   // floats per operand tile
#define TILE_B  (TILE_F * 4)  // 18432 bytes
#define NST     3
#define STAGE_BYTES (2 * TILE_B)          // A + W
#define SMEM_DYN    (NST * STAGE_BYTES)   // 110592

// ----- scratch (static device globals; allocation-free rule) -----
__device__ float g_h[B_ * GC_];
__device__ float g_zpart[KSPLIT * B_ * ZLD];
__device__ float g_z[B_ * LAT_];
__device__ float g_d[B_ * GC_];

__device__ __forceinline__ float lrelu(float v) { return v >= 0.0f ? v : 0.1f * v; }

__device__ __forceinline__ uint32_t smem_u32(const void* p) {
    return (uint32_t)__cvta_generic_to_shared(p);
}
__device__ __forceinline__ void cp_async16(uint32_t dst, const void* src, int sz) {
    asm volatile("cp.async.cg.shared.global [%0], [%1], 16, %2;"
                 :: "r"(dst), "l"(src), "r"(sz));
}
#define CP_COMMIT() asm volatile("cp.async.commit_group;" ::: "memory")
#define CP_WAIT2()  asm volatile("cp.async.wait_group 2;" ::: "memory")
#define CP_WAIT0()  asm volatile("cp.async.wait_group 0;" ::: "memory")

__device__ __forceinline__ uint32_t to_tf32(float f) {
    uint32_t u;
    asm("cvt.rna.tf32.f32 %0, %1;" : "=r"(u) : "f"(f));
    return u;
}
__device__ __forceinline__ void mma_tf32(float c[4], uint32_t a0, uint32_t a1,
                                         uint32_t a2, uint32_t a3,
                                         uint32_t b0, uint32_t b1) {
    asm volatile(
        "mma.sync.aligned.m16n8k8.row.col.f32.tf32.tf32.f32 "
        "{%0,%1,%2,%3}, {%4,%5,%6,%7}, {%8,%9}, {%0,%1,%2,%3};"
        : "+f"(c[0]), "+f"(c[1]), "+f"(c[2]), "+f"(c[3])
        : "r"(a0), "r"(a1), "r"(a2), "r"(a3), "r"(b0), "r"(b1));
}

// ---------------------------------------------------------------------------
// K1: encoder grouped conv
// ---------------------------------------------------------------------------
__global__ void __launch_bounds__(192)
enc_conv_kernel(const float* __restrict__ x, const float* __restrict__ ew,
                const float* __restrict__ eb) {
    __shared__ float sx[64 * KW_];
    const int b  = blockIdx.y;
    const int g0 = blockIdx.x * 64;
    const int ng = (G_ - g0 < 64) ? (G_ - g0) : 64;
    const int nval = ng * KW_;
    for (int i = threadIdx.x; i < nval; i += 192)
        sx[i] = x[(size_t)b * INLEN_ + (size_t)g0 * KW_ + i];
    __syncthreads();
    const int j  = threadIdx.x;
    const int gl = j / 3;
    const int c  = j - gl * 3;
    const int g  = g0 + gl;
    if (gl < ng) {
        const float* w  = ew + (size_t)g * 60 + c * 20;
        const float* xv = sx + gl * KW_;
        float acc = eb[g * 3 + c];
#pragma unroll
        for (int k = 0; k < KW_; k++) acc = fmaf(xv[k], w[k], acc);
        g_h[(size_t)b * GC_ + g * 3 + c] = lrelu(acc);
    }
}

// ---------------------------------------------------------------------------
// tf32 mma.sync GEMM: C[128, ntile] (+)= A[128,K] x W[N,K]^T
//   mode 0: A=g_h, C=g_zpart + by*B_*ZLD (raw split-K partial)
//   mode 1: A=g_z, C=g_d, epilogue lrelu(acc + bias[n])
// 256 threads, block tile 128x128x32, warp grid 2x4 (warp tile 64x32),
// 3-stage cp.async pipeline, pad-36 SMEM rows.
// ---------------------------------------------------------------------------
__global__ void __launch_bounds__(256, 1)
gemm_tc(const float* __restrict__ Wg, const float* __restrict__ bias,
        int lda, int ldw, int ldc, int Ntot, int Ktot, int mode)
{
    extern __shared__ float smem[];
    const int tid  = threadIdx.x;
    const int lane = tid & 31;
    const int wid  = tid >> 5;
    const int gq   = lane >> 2;    // group id 0..7
    const int tg   = lane & 3;     // thread-in-group 0..3
    const int wm   = wid >> 2;     // 0..1  (M)
    const int wn   = wid & 3;      // 0..3  (N)

    const int n0 = blockIdx.x * 128;
    const int k0 = blockIdx.y * KCHUNK;
    const int k1 = (k0 + KCHUNK < Ktot) ? (k0 + KCHUNK) : Ktot;
    const int T  = (k1 - k0 + BK - 1) >> 5;

    const float* A = (mode == 0) ? g_h : g_z;
    float* C = (mode == 0) ? (g_zpart + (size_t)blockIdx.y * (B_ * (size_t)ZLD))
                           : g_d;

    const uint32_t sbase = smem_u32(smem);

    // loader mapping: 1024 16B-segments per operand tile; 4 per thread.
    auto load_tile = [&](int t, int s) {
        const int kb = k0 + (t << 5);
        const uint32_t sa = sbase + (uint32_t)s * STAGE_BYTES;
        const uint32_t sw = sa + TILE_B;
#pragma unroll
        for (int u = 0; u < 4; u++) {
            const int f   = tid + u * 256;
            const int row = f >> 3;
            const int seg = f & 7;
            const int kk  = kb + seg * 4;
            const int okA = (kk + 4 <= k1) ? 16 : 0;
            const uint32_t doff = (uint32_t)(row * (SAK * 4) + seg * 16);
            cp_async16(sa + doff, okA ? (A + (size_t)row * lda + kk) : A, okA);
            const int n   = n0 + row;
            const int okW = (okA && n < Ntot) ? 16 : 0;
            cp_async16(sw + doff, okW ? (Wg + (size_t)n * ldw + kk) : Wg, okW);
        }
        CP_COMMIT();
    };

    float acc[4][4][4];
#pragma unroll
    for (int i = 0; i < 4; i++)
#pragma unroll
        for (int j = 0; j < 4; j++)
#pragma unroll
            for (int r = 0; r < 4; r++) acc[i][j][r] = 0.0f;

    load_tile(0, 0);
    if (T > 1) load_tile(1, 1);
    if (T > 2) load_tile(2, 2);

    for (int t = 0; t < T; t++) {
        const int s = t % NST;
        if (t + NST <= T) { CP_WAIT2(); } else { CP_WAIT0(); }
        __syncthreads();

        const float* As = smem + (size_t)s * (STAGE_BYTES / 4);
        const float* Ws = As + TILE_F;
#pragma unroll
        for (int ks = 0; ks < 4; ks++) {
            const int kk0 = ks * 8;
            uint32_t af[4][4];
#pragma unroll
            for (int i = 0; i < 4; i++) {
                const int rb = wm * 64 + i * 16;
                const float* ap = As + (size_t)(rb + gq) * SAK + kk0 + tg;
                af[i][0] = to_tf32(ap[0]);
                af[i][2] = to_tf32(ap[4]);
                af[i][1] = to_tf32(ap[8 * SAK]);
                af[i][3] = to_tf32(ap[8 * SAK + 4]);
            }
#pragma unroll
            for (int j = 0; j < 4; j++) {
                const int n = wn * 32 + j * 8 + gq;
                const float* wp = Ws + (size_t)n * SAK + kk0 + tg;
                const uint32_t b0 = to_tf32(wp[0]);
                const uint32_t b1 = to_tf32(wp[4]);
#pragma unroll
                for (int i = 0; i < 4; i++)
                    mma_tf32(acc[i][j], af[i][0], af[i][1], af[i][2], af[i][3],
                             b0, b1);
            }
        }
        __syncthreads();
        if (t + NST < T) load_tile(t + NST, s);
    }

    // epilogue
#pragma unroll
    for (int i = 0; i < 4; i++) {
        const int row = wm * 64 + i * 16 + gq;
#pragma unroll
        for (int j = 0; j < 4; j++) {
            const int col = n0 + wn * 32 + j * 8 + 2 * tg;
            float v0 = acc[i][j][0], v1 = acc[i][j][1];
            float v2 = acc[i][j][2], v3 = acc[i][j][3];
            if (mode == 1) {
                if (col >= Ntot) continue;
                const float b0 = bias[col], b1 = bias[col + 1];
                v0 = lrelu(v0 + b0); v1 = lrelu(v1 + b1);
                v2 = lrelu(v2 + b0); v3 = lrelu(v3 + b1);
            }
            *(float2*)(C + (size_t)row * ldc + col) = make_float2(v0, v1);
            *(float2*)(C + (size_t)(row + 8) * ldc + col) = make_float2(v2, v3);
        }
    }
}

// ---------------------------------------------------------------------------
// K3: split-K reduce + bias + leaky -> g_z
// ---------------------------------------------------------------------------
__global__ void __launch_bounds__(256)
reduce_z(const float* __restrict__ bias) {
    int idx = blockIdx.x * 256 + threadIdx.x;
    if (idx >= B_ * LAT_) return;
    int b = idx / LAT_;
    int n = idx - b * LAT_;
    float s = bias[n];
#pragma unroll
    for (int sp = 0; sp < KSPLIT; sp++)
        s += g_zpart[(size_t)sp * B_ * ZLD + (size_t)b * ZLD + n];
    g_z[idx] = lrelu(s);
}

// ---------------------------------------------------------------------------
// K5: decoder grouped conv-transpose + sigmoid
// ---------------------------------------------------------------------------
__global__ void __launch_bounds__(256)
dec_kernel(const float* __restrict__ dw, const float* __restrict__ db,
           float* __restrict__ out) {
    int idx = blockIdx.x * 256 + threadIdx.x;
    if (idx >= B_ * INLEN_) return;
    int b = idx / INLEN_;
    int pos = idx - b * INLEN_;
    int g = pos / KW_;
    int k = pos - g * KW_;
    const float* dd = g_d + (size_t)b * GC_ + g * 3;
    const float* w  = dw + (size_t)g * 60 + k;
    float acc = db[g];
    acc = fmaf(dd[0], w[0],  acc);
    acc = fmaf(dd[1], w[20], acc);
    acc = fmaf(dd[2], w[40], acc);
    out[idx] = 1.0f / (1.0f + __expf(-acc));
}

// ---------------------------------------------------------------------------
extern "C" void kernel_launch(void* const* d_in, const int* in_sizes, int n_in,
                              void* d_out, int out_size) {
    const float* x        = (const float*)d_in[0];
    const float* enc_w    = (const float*)d_in[1];
    const float* enc_b    = (const float*)d_in[2];
    const float* enc_fc_w = (const float*)d_in[3];
    const float* enc_fc_b = (const float*)d_in[4];
    const float* dec_fc_w = (const float*)d_in[5];
    const float* dec_fc_b = (const float*)d_in[6];
    const float* dec_w    = (const float*)d_in[7];
    const float* dec_b    = (const float*)d_in[8];
    float* out = (float*)d_out;

    static int smem_set = 0;
    if (!smem_set) {
        cudaFuncSetAttribute(gemm_tc,
                             cudaFuncAttributeMaxDynamicSharedMemorySize,
                             SMEM_DYN);
        smem_set = 1;
    }

    // 1) encoder grouped conv -> g_h [128, 30000]
    enc_conv_kernel<<<dim3(157, 128), 192>>>(x, enc_w, enc_b);

    // 2) enc FC tf32 mma, split-K=15 -> g_zpart  (W=[2000,30000])
    gemm_tc<<<dim3(16, KSPLIT), 256, SMEM_DYN>>>(enc_fc_w, nullptr,
                                                 GC_, GC_, ZLD, LAT_, GC_, 0);

    // 3) reduce + bias + leaky -> g_z [128, 2000]
    reduce_z<<<(B_ * LAT_ + 255) / 256, 256>>>(enc_fc_b);

    // 4) dec FC tf32 mma, fused epilogue -> g_d [128, 30000]  (W=[30000,2000])
    gemm_tc<<<dim3(235, 1), 256, SMEM_DYN>>>(dec_fc_w, dec_fc_b,
                                             LAT_, LAT_, GC_, GC_, LAT_, 1);

    // 5) decoder conv-transpose + sigmoid -> out [128, 200000]
    dec_kernel<<<(B_ * INLEN_ + 255) / 256, 256>>>(dec_w, dec_b, out);
}

// round 9
// speedup vs baseline: 2.8258x; 1.2177x over previous
#include <cuda_runtime.h>
#include <cstdint>

#define B_      128
#define G_      10000
#define KW_     20
#define GC_     30000
#define LAT_    2000
#define INLEN_  200000

#define KSPLIT  15
#define KCHUNK  2016          // 15*2016 >= 30000
#define ZLD     2048

#define BK      32
#define SAK     36            // padded row stride (floats) -> conflict-free frags
#define TILE_F  (128 * SAK)   // floats per operand tile
#define TILE_B  (TILE_F * 4)  // 18432 bytes
#define NST     2
#define STAGE_BYTES (2 * TILE_B)          // A + W
#define SMEM_DYN    (NST * STAGE_BYTES)   // 73728 -> 2 CTAs/SM

// ----- scratch (static device globals; allocation-free rule) -----
__device__ float g_h[B_ * GC_];
__device__ float g_zpart[KSPLIT * B_ * ZLD];
__device__ float g_z[B_ * LAT_];
__device__ float g_d[B_ * GC_];

__device__ __forceinline__ float lrelu(float v) { return v >= 0.0f ? v : 0.1f * v; }

__device__ __forceinline__ uint32_t smem_u32(const void* p) {
    return (uint32_t)__cvta_generic_to_shared(p);
}
__device__ __forceinline__ void cp_async16(uint32_t dst, const void* src, int sz) {
    asm volatile("cp.async.cg.shared.global [%0], [%1], 16, %2;"
                 :: "r"(dst), "l"(src), "r"(sz));
}
#define CP_COMMIT() asm volatile("cp.async.commit_group;" ::: "memory")
#define CP_WAITN()  asm volatile("cp.async.wait_group 1;" ::: "memory")
#define CP_WAIT0()  asm volatile("cp.async.wait_group 0;" ::: "memory")

// raw fp32 bits fed as tf32 operands: HW uses top bits (truncation).
// ~2.4e-4 coherent bias per GEMM, compressed by final sigmoid -> ~1e-4 final.
__device__ __forceinline__ void mma_tf32(float c[4], uint32_t a0, uint32_t a1,
                                         uint32_t a2, uint32_t a3,
                                         uint32_t b0, uint32_t b1) {
    asm volatile(
        "mma.sync.aligned.m16n8k8.row.col.f32.tf32.tf32.f32 "
        "{%0,%1,%2,%3}, {%4,%5,%6,%7}, {%8,%9}, {%0,%1,%2,%3};"
        : "+f"(c[0]), "+f"(c[1]), "+f"(c[2]), "+f"(c[3])
        : "r"(a0), "r"(a1), "r"(a2), "r"(a3), "r"(b0), "r"(b1));
}

// ---------------------------------------------------------------------------
// K1: encoder grouped conv
// ---------------------------------------------------------------------------
__global__ void __launch_bounds__(192)
enc_conv_kernel(const float* __restrict__ x, const float* __restrict__ ew,
                const float* __restrict__ eb) {
    __shared__ float sx[64 * KW_];
    const int b  = blockIdx.y;
    const int g0 = blockIdx.x * 64;
    const int ng = (G_ - g0 < 64) ? (G_ - g0) : 64;
    const int nval = ng * KW_;
    for (int i = threadIdx.x; i < nval; i += 192)
        sx[i] = x[(size_t)b * INLEN_ + (size_t)g0 * KW_ + i];
    __syncthreads();
    const int j  = threadIdx.x;
    const int gl = j / 3;
    const int c  = j - gl * 3;
    const int g  = g0 + gl;
    if (gl < ng) {
        const float* w  = ew + (size_t)g * 60 + c * 20;
        const float* xv = sx + gl * KW_;
        float acc = eb[g * 3 + c];
#pragma unroll
        for (int k = 0; k < KW_; k++) acc = fmaf(xv[k], w[k], acc);
        g_h[(size_t)b * GC_ + g * 3 + c] = lrelu(acc);
    }
}

// ---------------------------------------------------------------------------
// tf32 mma.sync GEMM: C[128, ntile] (+)= A[128,K] x W[N,K]^T
//   mode 0: A=g_h, C=g_zpart + by*B_*ZLD (raw split-K partial)
//   mode 1: A=g_z, C=g_d, epilogue lrelu(acc + bias[n])
// 256 threads, block tile 128x128x32, warp grid 2x4 (warp tile 64x32),
// 2-stage cp.async pipeline, 2 CTAs/SM.
// ---------------------------------------------------------------------------
__global__ void __launch_bounds__(256, 2)
gemm_tc(const float* __restrict__ Wg, const float* __restrict__ bias,
        int lda, int ldw, int ldc, int Ntot, int Ktot, int mode)
{
    extern __shared__ float smem[];
    const int tid  = threadIdx.x;
    const int lane = tid & 31;
    const int wid  = tid >> 5;
    const int gq   = lane >> 2;    // group id 0..7
    const int tg   = lane & 3;     // thread-in-group 0..3
    const int wm   = wid >> 2;     // 0..1  (M)
    const int wn   = wid & 3;      // 0..3  (N)

    const int n0 = blockIdx.x * 128;
    const int k0 = blockIdx.y * KCHUNK;
    const int k1 = (k0 + KCHUNK < Ktot) ? (k0 + KCHUNK) : Ktot;
    const int T  = (k1 - k0 + BK - 1) >> 5;

    const float* A = (mode == 0) ? g_h : g_z;
    float* C = (mode == 0) ? (g_zpart + (size_t)blockIdx.y * (B_ * (size_t)ZLD))
                           : g_d;

    const uint32_t sbase = smem_u32(smem);

    // loader mapping: 1024 16B-segments per operand tile; 4 per thread.
    auto load_tile = [&](int t, int s) {
        const int kb = k0 + (t << 5);
        const uint32_t sa = sbase + (uint32_t)s * STAGE_BYTES;
        const uint32_t sw = sa + TILE_B;
#pragma unroll
        for (int u = 0; u < 4; u++) {
            const int f   = tid + u * 256;
            const int row = f >> 3;
            const int seg = f & 7;
            const int kk  = kb + seg * 4;
            const int okA = (kk + 4 <= k1) ? 16 : 0;
            const uint32_t doff = (uint32_t)(row * (SAK * 4) + seg * 16);
            cp_async16(sa + doff, okA ? (A + (size_t)row * lda + kk) : A, okA);
            const int n   = n0 + row;
            const int okW = (okA && n < Ntot) ? 16 : 0;
            cp_async16(sw + doff, okW ? (Wg + (size_t)n * ldw + kk) : Wg, okW);
        }
        CP_COMMIT();
    };

    float acc[4][4][4];
#pragma unroll
    for (int i = 0; i < 4; i++)
#pragma unroll
        for (int j = 0; j < 4; j++)
#pragma unroll
            for (int r = 0; r < 4; r++) acc[i][j][r] = 0.0f;

    load_tile(0, 0);
    if (T > 1) load_tile(1, 1);

    for (int t = 0; t < T; t++) {
        const int s = t & 1;
        if (t + NST <= T) { CP_WAITN(); } else { CP_WAIT0(); }
        __syncthreads();

        const float* As = smem + (size_t)s * (STAGE_BYTES / 4);
        const float* Ws = As + TILE_F;
#pragma unroll
        for (int ks = 0; ks < 4; ks++) {
            const int kk0 = ks * 8;
            uint32_t af[4][4];
#pragma unroll
            for (int i = 0; i < 4; i++) {
                const int rb = wm * 64 + i * 16;
                const float* ap = As + (size_t)(rb + gq) * SAK + kk0 + tg;
                af[i][0] = __float_as_uint(ap[0]);
                af[i][2] = __float_as_uint(ap[4]);
                af[i][1] = __float_as_uint(ap[8 * SAK]);
                af[i][3] = __float_as_uint(ap[8 * SAK + 4]);
            }
#pragma unroll
            for (int j = 0; j < 4; j++) {
                const int n = wn * 32 + j * 8 + gq;
                const float* wp = Ws + (size_t)n * SAK + kk0 + tg;
                const uint32_t b0 = __float_as_uint(wp[0]);
                const uint32_t b1 = __float_as_uint(wp[4]);
#pragma unroll
                for (int i = 0; i < 4; i++)
                    mma_tf32(acc[i][j], af[i][0], af[i][1], af[i][2], af[i][3],
                             b0, b1);
            }
        }
        __syncthreads();
        if (t + NST < T) load_tile(t + NST, s);
    }

    // epilogue
#pragma unroll
    for (int i = 0; i < 4; i++) {
        const int row = wm * 64 + i * 16 + gq;
#pragma unroll
        for (int j = 0; j < 4; j++) {
            const int col = n0 + wn * 32 + j * 8 + 2 * tg;
            float v0 = acc[i][j][0], v1 = acc[i][j][1];
            float v2 = acc[i][j][2], v3 = acc[i][j][3];
            if (mode == 1) {
                if (col >= Ntot) continue;
                const float b0 = bias[col], b1 = bias[col + 1];
                v0 = lrelu(v0 + b0); v1 = lrelu(v1 + b1);
                v2 = lrelu(v2 + b0); v3 = lrelu(v3 + b1);
            }
            *(float2*)(C + (size_t)row * ldc + col) = make_float2(v0, v1);
            *(float2*)(C + (size_t)(row + 8) * ldc + col) = make_float2(v2, v3);
        }
    }
}

// ---------------------------------------------------------------------------
// K3: split-K reduce + bias + leaky -> g_z
// ---------------------------------------------------------------------------
__global__ void __launch_bounds__(256)
reduce_z(const float* __restrict__ bias) {
    int idx = blockIdx.x * 256 + threadIdx.x;
    if (idx >= B_ * LAT_) return;
    int b = idx / LAT_;
    int n = idx - b * LAT_;
    float s = bias[n];
#pragma unroll
    for (int sp = 0; sp < KSPLIT; sp++)
        s += g_zpart[(size_t)sp * B_ * ZLD + (size_t)b * ZLD + n];
    g_z[idx] = lrelu(s);
}

// ---------------------------------------------------------------------------
// K5: decoder grouped conv-transpose + sigmoid (float4 vectorized)
// one thread -> 4 consecutive outputs within one group (KW=20 -> 5 quads)
// ---------------------------------------------------------------------------
__global__ void __launch_bounds__(256)
dec_kernel(const float* __restrict__ dw, const float* __restrict__ db,
           float* __restrict__ out) {
    int idx = blockIdx.x * 256 + threadIdx.x;
    if (idx >= B_ * G_ * 5) return;
    int b = idx / (G_ * 5);
    int r = idx - b * (G_ * 5);
    int g = r / 5;
    int q = (r - g * 5) * 4;

    const float* dd = g_d + (size_t)b * GC_ + g * 3;
    const float d0 = dd[0], d1 = dd[1], d2 = dd[2];
    const float* wb = dw + (size_t)g * 60 + q;
    const float4 w0 = *(const float4*)(wb);
    const float4 w1 = *(const float4*)(wb + 20);
    const float4 w2 = *(const float4*)(wb + 40);
    const float bs = db[g];

    float4 o;
    float a;
    a = bs + d0 * w0.x + d1 * w1.x + d2 * w2.x; o.x = 1.0f / (1.0f + __expf(-a));
    a = bs + d0 * w0.y + d1 * w1.y + d2 * w2.y; o.y = 1.0f / (1.0f + __expf(-a));
    a = bs + d0 * w0.z + d1 * w1.z + d2 * w2.z; o.z = 1.0f / (1.0f + __expf(-a));
    a = bs + d0 * w0.w + d1 * w1.w + d2 * w2.w; o.w = 1.0f / (1.0f + __expf(-a));
    *(float4*)(out + (size_t)b * INLEN_ + g * 20 + q) = o;
}

// ---------------------------------------------------------------------------
extern "C" void kernel_launch(void* const* d_in, const int* in_sizes, int n_in,
                              void* d_out, int out_size) {
    const float* x        = (const float*)d_in[0];
    const float* enc_w    = (const float*)d_in[1];
    const float* enc_b    = (const float*)d_in[2];
    const float* enc_fc_w = (const float*)d_in[3];
    const float* enc_fc_b = (const float*)d_in[4];
    const float* dec_fc_w = (const float*)d_in[5];
    const float* dec_fc_b = (const float*)d_in[6];
    const float* dec_w    = (const float*)d_in[7];
    const float* dec_b    = (const float*)d_in[8];
    float* out = (float*)d_out;

    cudaFuncSetAttribute(gemm_tc, cudaFuncAttributeMaxDynamicSharedMemorySize,
                         SMEM_DYN);

    // 1) encoder grouped conv -> g_h [128, 30000]
    enc_conv_kernel<<<dim3(157, 128), 192>>>(x, enc_w, enc_b);

    // 2) enc FC tf32 mma, split-K=15 -> g_zpart  (W=[2000,30000])
    gemm_tc<<<dim3(16, KSPLIT), 256, SMEM_DYN>>>(enc_fc_w, nullptr,
                                                 GC_, GC_, ZLD, LAT_, GC_, 0);

    // 3) reduce + bias + leaky -> g_z [128, 2000]
    reduce_z<<<(B_ * LAT_ + 255) / 256, 256>>>(enc_fc_b);

    // 4) dec FC tf32 mma, fused epilogue -> g_d [128, 30000]  (W=[30000,2000])
    gemm_tc<<<dim3(235, 1), 256, SMEM_DYN>>>(dec_fc_w, dec_fc_b,
                                             LAT_, LAT_, GC_, GC_, LAT_, 1);

    // 5) decoder conv-transpose + sigmoid -> out [128, 200000]
    dec_kernel<<<(B_ * G_ * 5 + 255) / 256, 256>>>(dec_w, dec_b, out);
}